// round 1
// baseline (speedup 1.0000x reference)
#include <cuda_runtime.h>
#include <cstdint>

#define H_HEADS 8
#define D_IN 64
#define D_H 32
#define B_SZ 32
#define N_NODES 512

// Scratch (static device globals: allowed; no runtime allocation)
__device__ float g_h[H_HEADS * B_SZ * N_NODES * D_H];    // 16 MB, [h][b][n][k]
__device__ float g_msgs[B_SZ * N_NODES * D_H];           // 2 MB, [b][n][k]

// ---------------------------------------------------------------------------
// Kernel 1: per-head projection h[h,b,n,k] = sum_d inputs[b,n,d] * linear[h,d,k]
// Also zero-inits g_msgs (grid-stride).
// grid = H*B = 256 blocks, 256 threads
// ---------------------------------------------------------------------------
__global__ void proj_kernel(const float* __restrict__ inputs,
                            const float* __restrict__ linear) {
    const int hb = blockIdx.x;
    const int h = hb >> 5;          // hb = h*32 + b
    const int b = hb & 31;

    __shared__ float Wsm[D_IN * D_H];   // 8 KB
    __shared__ float xsm[8 * D_IN];     // 2 KB

    const float* W = linear + h * D_IN * D_H;
    for (int i = threadIdx.x; i < D_IN * D_H; i += 256) Wsm[i] = W[i];

    // zero msgs accumulator (stream-ordered before att_kernel's atomics)
    for (int i = blockIdx.x * 256 + threadIdx.x; i < B_SZ * N_NODES * D_H;
         i += 256 * 256)
        g_msgs[i] = 0.f;

    __syncthreads();

    const int r = threadIdx.x >> 5;   // 0..7 (row in chunk)
    const int k = threadIdx.x & 31;   // output column
    const float* xb = inputs + (size_t)b * N_NODES * D_IN;
    float* out = g_h + (size_t)hb * N_NODES * D_H;

    for (int n0 = 0; n0 < N_NODES; n0 += 8) {
        for (int i = threadIdx.x; i < 8 * D_IN; i += 256)
            xsm[i] = xb[n0 * D_IN + i];
        __syncthreads();
        float acc = 0.f;
#pragma unroll
        for (int d = 0; d < D_IN; d++)
            acc = fmaf(xsm[r * D_IN + d], Wsm[d * D_H + k], acc);
        out[(n0 + r) * D_H + k] = acc;
        __syncthreads();
    }
}

// ---------------------------------------------------------------------------
// Kernel 2: attention softmax + weighted aggregation for one (h,b) pair,
// split into 2 row-halves per block for occupancy/balance.
// grid = H*B*2 = 512 blocks, 256 threads. One thread = one output row.
// Dynamic smem: h tile [512][32] (64 KB) + e_src[512] + e_tar[512].
// ---------------------------------------------------------------------------
__global__ void att_kernel(const float* __restrict__ att_src,
                           const float* __restrict__ att_tar) {
    extern __shared__ float smem[];
    float* hsm = smem;                         // 512*32 floats
    float* esrc = smem + N_NODES * D_H;        // 512
    float* etar = esrc + N_NODES;              // 512

    const int blk = blockIdx.x;
    const int half = blk & 1;
    const int hb = blk >> 1;
    const int h = hb >> 5;

    // load h tile (64 KB) via float4
    {
        const float4* src = (const float4*)(g_h + (size_t)hb * N_NODES * D_H);
        float4* dst = (float4*)hsm;
        for (int i = threadIdx.x; i < N_NODES * D_H / 4; i += 256)
            dst[i] = src[i];
    }
    __syncthreads();

    const int wid = threadIdx.x >> 5;
    const int lane = threadIdx.x & 31;

    // e_src[j] = h[j,:]·att_src[h], e_tar[j] = h[j,:]·att_tar[h]
    {
        const float as = att_src[h * D_H + lane];
        const float at = att_tar[h * D_H + lane];
        for (int j = wid; j < N_NODES; j += 8) {
            float v = hsm[j * D_H + lane];
            float s1 = v * as;
            float s2 = v * at;
#pragma unroll
            for (int off = 16; off; off >>= 1) {
                s1 += __shfl_xor_sync(0xffffffffu, s1, off);
                s2 += __shfl_xor_sync(0xffffffffu, s2, off);
            }
            if (lane == 0) { esrc[j] = s1; etar[j] = s2; }
        }
    }
    __syncthreads();

    const int row = half * 256 + threadIdx.x;
    const float et = etar[row];

    // pass 1: row max of leaky_relu(et + e_src[j]), UNMASKED.
    // Unmasked max >= masked max, so exp never overflows; softmax ratios are
    // invariant to the max offset, and the self term is subtracted after.
    float m = -1e30f;
    for (int j = 0; j < N_NODES; j++) {
        float s = et + esrc[j];
        float ls = fmaxf(s, 0.f) + 0.2f * fminf(s, 0.f);
        m = fmaxf(m, ls);
    }
    const float L2E = 1.4426950408889634f;
    const float negml = -m * L2E;

    // pass 2: p_j = 2^((ls_j - m)*log2e); acc[k] += p_j * h[j][k] (f32x2 packed)
    unsigned long long acc[16];
#pragma unroll
    for (int i = 0; i < 16; i++) acc[i] = 0ull;
    float sum = 0.f;

    const ulonglong2* hbase = (const ulonglong2*)hsm;  // 8 × 16B per row
#pragma unroll 2
    for (int j = 0; j < N_NODES; j++) {
        float s = et + esrc[j];
        float ls = fmaxf(s, 0.f) + 0.2f * fminf(s, 0.f);
        float t = fmaf(ls, L2E, negml);
        float p;
        asm("ex2.approx.f32 %0, %1;" : "=f"(p) : "f"(t));
        sum += p;
        unsigned long long p2;
        asm("mov.b64 %0, {%1, %1};" : "=l"(p2) : "f"(p));
        const ulonglong2* hr = hbase + j * 8;
#pragma unroll
        for (int c = 0; c < 8; c++) {
            ulonglong2 hv = hr[c];
            asm("fma.rn.f32x2 %0, %1, %2, %0;" : "+l"(acc[2 * c])     : "l"(hv.x), "l"(p2));
            asm("fma.rn.f32x2 %0, %1, %2, %0;" : "+l"(acc[2 * c + 1]) : "l"(hv.y), "l"(p2));
        }
    }

    // subtract the (masked) self term once
    float sself = et + esrc[row];
    float lself = fmaxf(sself, 0.f) + 0.2f * fminf(sself, 0.f);
    float tself = fmaf(lself, L2E, negml);
    float pself;
    asm("ex2.approx.f32 %0, %1;" : "=f"(pself) : "f"(tself));
    sum -= pself;

    const float scale = 0.125f / sum;  // 1/H folded in
    const int b = hb & 31;
    float* msgrow = g_msgs + ((size_t)b * N_NODES + row) * D_H;
    const float* hself = hsm + row * D_H;
#pragma unroll
    for (int c = 0; c < 16; c++) {
        float v0 = __uint_as_float((unsigned)(acc[c] & 0xffffffffull));
        float v1 = __uint_as_float((unsigned)(acc[c] >> 32));
        int k0 = 2 * c, k1 = 2 * c + 1;
        v0 = (v0 - pself * hself[k0]) * scale;
        v1 = (v1 - pself * hself[k1]) * scale;
        atomicAdd(msgrow + k0, v0);
        atomicAdd(msgrow + k1, v1);
    }
}

// ---------------------------------------------------------------------------
// Kernel 3: msgs = tanh(msgs + bias); GRU-style gated update -> out
// grid = B * 8 (64-row chunks) = 256 blocks, 256 threads
// Dynamic smem: Wir/Wii/Win (3*64*32) + Whr/Whi/Whm (3*32*32) + x[64][64] + m[64][32]
// ---------------------------------------------------------------------------
__global__ void gru_kernel(const float* __restrict__ inputs,
                           const float* __restrict__ hidden,
                           const float* __restrict__ bias,
                           const float* __restrict__ W_hr,
                           const float* __restrict__ W_hi,
                           const float* __restrict__ W_hm,
                           const float* __restrict__ W_ir,
                           const float* __restrict__ b_ir,
                           const float* __restrict__ W_ii,
                           const float* __restrict__ b_ii,
                           const float* __restrict__ W_in,
                           const float* __restrict__ b_in,
                           float* __restrict__ out) {
    extern __shared__ float smem[];
    float* Wir = smem;                    // 2048
    float* Wii = Wir + D_IN * D_H;        // 2048
    float* Win = Wii + D_IN * D_H;        // 2048
    float* Whr = Win + D_IN * D_H;        // 1024
    float* Whi = Whr + D_H * D_H;         // 1024
    float* Whm = Whi + D_H * D_H;         // 1024
    float* xsm = Whm + D_H * D_H;         // 64*64
    float* msm = xsm + 64 * D_IN;         // 64*32

    const int b = blockIdx.x >> 3;
    const int n0 = (blockIdx.x & 7) * 64;

    for (int i = threadIdx.x; i < D_IN * D_H; i += 256) {
        Wir[i] = W_ir[i]; Wii[i] = W_ii[i]; Win[i] = W_in[i];
    }
    for (int i = threadIdx.x; i < D_H * D_H; i += 256) {
        Whr[i] = W_hr[i]; Whi[i] = W_hi[i]; Whm[i] = W_hm[i];
    }
    for (int i = threadIdx.x; i < 64 * D_IN; i += 256)
        xsm[i] = inputs[((size_t)b * N_NODES + n0) * D_IN + i];
    for (int i = threadIdx.x; i < 64 * D_H; i += 256)
        msm[i] = tanhf(g_msgs[((size_t)b * N_NODES + n0) * D_H + i] + bias[i & 31]);
    __syncthreads();

    const int k = threadIdx.x & 31;
    const int r0 = threadIdx.x >> 5;

    for (int e = 0; e < 8; e++) {
        const int r = r0 + 8 * e;
        float xr = b_ir[k], xi = b_ii[k], xn = b_in[k];
#pragma unroll 8
        for (int d = 0; d < D_IN; d++) {
            float x = xsm[r * D_IN + d];
            xr = fmaf(x, Wir[d * D_H + k], xr);
            xi = fmaf(x, Wii[d * D_H + k], xi);
            xn = fmaf(x, Win[d * D_H + k], xn);
        }
        float hr = 0.f, hi = 0.f, hm = 0.f;
#pragma unroll 8
        for (int d = 0; d < D_H; d++) {
            float mm = msm[r * D_H + d];
            hr = fmaf(mm, Whr[d * D_H + k], hr);
            hi = fmaf(mm, Whi[d * D_H + k], hi);
            hm = fmaf(mm, Whm[d * D_H + k], hm);
        }
        float mg = 1.f / (1.f + __expf(-(xr + hr)));
        float ig = 1.f / (1.f + __expf(-(xi + hi)));
        float nn = tanhf(xn + mg * hm);
        const size_t idx = ((size_t)b * N_NODES + n0 + r) * D_H + k;
        out[idx] = ig * nn + (1.f - ig) * hidden[idx];
    }
}

// ---------------------------------------------------------------------------
// Launch
// ---------------------------------------------------------------------------
extern "C" void kernel_launch(void* const* d_in, const int* in_sizes, int n_in,
                              void* d_out, int out_size) {
    const float* inputs  = (const float*)d_in[0];
    const float* hidden  = (const float*)d_in[1];
    const float* linear  = (const float*)d_in[2];
    const float* bias    = (const float*)d_in[3];
    const float* att_src = (const float*)d_in[4];
    const float* att_tar = (const float*)d_in[5];
    const float* W_hr    = (const float*)d_in[6];
    const float* W_hi    = (const float*)d_in[7];
    const float* W_hm    = (const float*)d_in[8];
    const float* W_ir    = (const float*)d_in[9];
    const float* b_ir    = (const float*)d_in[10];
    const float* W_ii    = (const float*)d_in[11];
    const float* b_ii    = (const float*)d_in[12];
    const float* W_in    = (const float*)d_in[13];
    const float* b_in    = (const float*)d_in[14];
    float* out = (float*)d_out;

    const int att_smem = (N_NODES * D_H + 2 * N_NODES) * sizeof(float);   // 69632
    const int gru_smem = (3 * D_IN * D_H + 3 * D_H * D_H + 64 * D_IN + 64 * D_H)
                         * sizeof(float);                                  // 61440

    static bool attr_done = false;
    if (!attr_done) {
        cudaFuncSetAttribute(att_kernel, cudaFuncAttributeMaxDynamicSharedMemorySize,
                             att_smem);
        cudaFuncSetAttribute(gru_kernel, cudaFuncAttributeMaxDynamicSharedMemorySize,
                             gru_smem);
        attr_done = true;
    }

    proj_kernel<<<H_HEADS * B_SZ, 256>>>(inputs, linear);
    att_kernel<<<H_HEADS * B_SZ * 2, 256, att_smem>>>(att_src, att_tar);
    gru_kernel<<<B_SZ * 8, 256, gru_smem>>>(inputs, hidden, bias,
                                            W_hr, W_hi, W_hm,
                                            W_ir, b_ir, W_ii, b_ii, W_in, b_in,
                                            out);
}

// round 2
// speedup vs baseline: 1.3002x; 1.3002x over previous
#include <cuda_runtime.h>
#include <cstdint>

#define H_HEADS 8
#define D_IN 64
#define D_H 32
#define B_SZ 32
#define N_NODES 512

// Scratch (static device globals: allowed; no runtime allocation)
__device__ float g_h[H_HEADS * B_SZ * N_NODES * D_H];    // 16 MB, [h][b][n][k]
__device__ float g_msgs[B_SZ * N_NODES * D_H];           // 2 MB, [b][n][k]

__device__ __forceinline__ unsigned long long pack2(float x) {
    unsigned long long r;
    asm("mov.b64 %0, {%1, %1};" : "=l"(r) : "f"(x));
    return r;
}
__device__ __forceinline__ void ffma2(unsigned long long& acc,
                                      unsigned long long a,
                                      unsigned long long b) {
    asm("fma.rn.f32x2 %0, %1, %2, %0;" : "+l"(acc) : "l"(a), "l"(b));
}
__device__ __forceinline__ float lo32(unsigned long long v) {
    return __uint_as_float((unsigned)(v & 0xffffffffull));
}
__device__ __forceinline__ float hi32(unsigned long long v) {
    return __uint_as_float((unsigned)(v >> 32));
}

// ---------------------------------------------------------------------------
// Kernel 1: h[h,b,n,k] = sum_d inputs[b,n,d] * linear[h,d,k]
// grid = H*B*4 (128-row segments), 256 threads.
// Thread = 4 rows x 4 cols, f32x2 packed accumulation.
// Also zero-inits g_msgs.
// ---------------------------------------------------------------------------
__global__ void __launch_bounds__(256) proj_kernel(const float* __restrict__ inputs,
                                                   const float* __restrict__ linear) {
    const int blk = blockIdx.x;
    const int hb = blk >> 2;
    const int seg = blk & 3;
    const int h = hb >> 5;
    const int b = hb & 31;

    __shared__ __align__(16) float Wsm[D_IN * D_H];   // 8 KB
    __shared__ __align__(16) float xsm[128 * D_IN];   // 32 KB

    {
        const float4* W4 = (const float4*)(linear + h * D_IN * D_H);
        float4* Ws4 = (float4*)Wsm;
        for (int i = threadIdx.x; i < D_IN * D_H / 4; i += 256) Ws4[i] = W4[i];
        const float4* x4 = (const float4*)(inputs +
                           ((size_t)b * N_NODES + seg * 128) * D_IN);
        float4* xs4 = (float4*)xsm;
        for (int i = threadIdx.x; i < 128 * D_IN / 4; i += 256) xs4[i] = x4[i];
    }
    // zero msgs accumulator (stream-ordered before att_kernel's atomics)
    for (int i = blk * 256 + threadIdx.x; i < B_SZ * N_NODES * D_H; i += 1024 * 256)
        g_msgs[i] = 0.f;
    __syncthreads();

    const int k4 = threadIdx.x & 7;        // 16B column chunk (4 cols)
    const int r0 = (threadIdx.x >> 3) * 4; // local row base (0..124)

    unsigned long long acc[4][2];
#pragma unroll
    for (int ri = 0; ri < 4; ri++) { acc[ri][0] = 0ull; acc[ri][1] = 0ull; }

    const ulonglong2* Wu = (const ulonglong2*)Wsm;  // 8 x 16B per d-row

    for (int d0 = 0; d0 < D_IN; d0 += 4) {
        float4 xv[4];
#pragma unroll
        for (int ri = 0; ri < 4; ri++)
            xv[ri] = *(const float4*)&xsm[(r0 + ri) * D_IN + d0];
#pragma unroll
        for (int dd = 0; dd < 4; dd++) {
            ulonglong2 wv = Wu[(d0 + dd) * 8 + k4];
#pragma unroll
            for (int ri = 0; ri < 4; ri++) {
                unsigned long long x2 = pack2(((const float*)&xv[ri])[dd]);
                ffma2(acc[ri][0], wv.x, x2);
                ffma2(acc[ri][1], wv.y, x2);
            }
        }
    }

    float* out = g_h + ((size_t)hb * N_NODES + seg * 128) * D_H;
#pragma unroll
    for (int ri = 0; ri < 4; ri++) {
        float4 v;
        v.x = lo32(acc[ri][0]); v.y = hi32(acc[ri][0]);
        v.z = lo32(acc[ri][1]); v.w = hi32(acc[ri][1]);
        *(float4*)&out[(r0 + ri) * D_H + k4 * 4] = v;
    }
}

// ---------------------------------------------------------------------------
// Kernel 2: attention softmax + weighted aggregation, one (h,b) pair per 2
// blocks (row halves). 256 threads, one thread = one output row.
// Key trick: leaky_relu is monotone, so the row max is
//   lrelu(et + max_j esrc[j]) -- one block-wide reduce, no per-row max pass.
// ---------------------------------------------------------------------------
__global__ void __launch_bounds__(256, 2) att_kernel(const float* __restrict__ att_src,
                                                     const float* __restrict__ att_tar) {
    extern __shared__ float smem[];
    float* hsm = smem;                         // 512*32
    float* esrc = smem + N_NODES * D_H;        // 512
    float* etar = esrc + N_NODES;              // 512
    float* esmaxp = etar + N_NODES;            // 1

    const int blk = blockIdx.x;
    const int half = blk & 1;
    const int hb = blk >> 1;
    const int h = hb >> 5;

    // load h tile (64 KB)
    {
        const float4* src = (const float4*)(g_h + (size_t)hb * N_NODES * D_H);
        float4* dst = (float4*)hsm;
        for (int i = threadIdx.x; i < N_NODES * D_H / 4; i += 256)
            dst[i] = src[i];
    }
    __syncthreads();

    const int wid = threadIdx.x >> 5;
    const int lane = threadIdx.x & 31;

    // e_src[j] = h[j,:]·att_src[h], e_tar[j] = h[j,:]·att_tar[h]
    {
        const float as = att_src[h * D_H + lane];
        const float at = att_tar[h * D_H + lane];
        for (int j = wid; j < N_NODES; j += 8) {
            float v = hsm[j * D_H + lane];
            float s1 = v * as;
            float s2 = v * at;
#pragma unroll
            for (int off = 16; off; off >>= 1) {
                s1 += __shfl_xor_sync(0xffffffffu, s1, off);
                s2 += __shfl_xor_sync(0xffffffffu, s2, off);
            }
            if (lane == 0) { esrc[j] = s1; etar[j] = s2; }
        }
    }
    __syncthreads();

    // block-wide max of esrc (warp 0)
    if (wid == 0) {
        float mx = -1e30f;
        for (int j = lane; j < N_NODES; j += 32) mx = fmaxf(mx, esrc[j]);
#pragma unroll
        for (int off = 16; off; off >>= 1)
            mx = fmaxf(mx, __shfl_xor_sync(0xffffffffu, mx, off));
        if (lane == 0) *esmaxp = mx;
    }
    __syncthreads();

    const int row = half * 256 + threadIdx.x;
    const float et = etar[row];
    const float esmax = *esmaxp;

    const float L2E = 1.4426950408889634f;
    const float C2 = 0.2f * 1.4426950408889634f;

    // unmasked row max (monotone lrelu): exact, and softmax ratios are
    // shift-invariant; self term removed after the loop.
    const float smax = et + esmax;
    const float m = fmaxf(smax, 0.f) + 0.2f * fminf(smax, 0.f);
    const float negml = -m * L2E;

    unsigned long long acc[16];
#pragma unroll
    for (int i = 0; i < 16; i++) acc[i] = 0ull;
    float sum = 0.f;

    const ulonglong2* hbase = (const ulonglong2*)hsm;
    const float4* esrc4 = (const float4*)esrc;

    for (int j4 = 0; j4 < N_NODES / 4; j4++) {
        float4 es = esrc4[j4];
#pragma unroll
        for (int jj = 0; jj < 4; jj++) {
            float s = et + ((const float*)&es)[jj];
            float t = fmaf(fmaxf(s, 0.f), L2E, fmaf(fminf(s, 0.f), C2, negml));
            float p;
            asm("ex2.approx.f32 %0, %1;" : "=f"(p) : "f"(t));
            sum += p;
            unsigned long long p2 = pack2(p);
            const ulonglong2* hr = hbase + (j4 * 4 + jj) * 8;
#pragma unroll
            for (int c = 0; c < 8; c++) {
                ulonglong2 hv = hr[c];
                ffma2(acc[2 * c], hv.x, p2);
                ffma2(acc[2 * c + 1], hv.y, p2);
            }
        }
    }

    // subtract the masked self term once
    float sself = et + esrc[row];
    float tself = fmaf(fmaxf(sself, 0.f), L2E, fmaf(fminf(sself, 0.f), C2, negml));
    float pself;
    asm("ex2.approx.f32 %0, %1;" : "=f"(pself) : "f"(tself));
    sum -= pself;

    const float scale = 0.125f / sum;  // 1/H folded in
    const int b = hb & 31;
    float* msgrow = g_msgs + ((size_t)b * N_NODES + row) * D_H;
    const float* hself = hsm + row * D_H;
#pragma unroll
    for (int c = 0; c < 16; c++) {
        float v0 = lo32(acc[c]);
        float v1 = hi32(acc[c]);
        int k0 = 2 * c, k1 = 2 * c + 1;
        v0 = (v0 - pself * hself[k0]) * scale;
        v1 = (v1 - pself * hself[k1]) * scale;
        atomicAdd(msgrow + k0, v0);
        atomicAdd(msgrow + k1, v1);
    }
}

// ---------------------------------------------------------------------------
// Kernel 3: msgs = tanh(msgs + bias); GRU-style gated update -> out
// grid = B * 8 (64-row chunks), 256 threads
// ---------------------------------------------------------------------------
__global__ void gru_kernel(const float* __restrict__ inputs,
                           const float* __restrict__ hidden,
                           const float* __restrict__ bias,
                           const float* __restrict__ W_hr,
                           const float* __restrict__ W_hi,
                           const float* __restrict__ W_hm,
                           const float* __restrict__ W_ir,
                           const float* __restrict__ b_ir,
                           const float* __restrict__ W_ii,
                           const float* __restrict__ b_ii,
                           const float* __restrict__ W_in,
                           const float* __restrict__ b_in,
                           float* __restrict__ out) {
    extern __shared__ float smem[];
    float* Wir = smem;                    // 2048
    float* Wii = Wir + D_IN * D_H;        // 2048
    float* Win = Wii + D_IN * D_H;        // 2048
    float* Whr = Win + D_IN * D_H;        // 1024
    float* Whi = Whr + D_H * D_H;         // 1024
    float* Whm = Whi + D_H * D_H;         // 1024
    float* xsm = Whm + D_H * D_H;         // 64*64
    float* msm = xsm + 64 * D_IN;         // 64*32

    const int b = blockIdx.x >> 3;
    const int n0 = (blockIdx.x & 7) * 64;

    for (int i = threadIdx.x; i < D_IN * D_H; i += 256) {
        Wir[i] = W_ir[i]; Wii[i] = W_ii[i]; Win[i] = W_in[i];
    }
    for (int i = threadIdx.x; i < D_H * D_H; i += 256) {
        Whr[i] = W_hr[i]; Whi[i] = W_hi[i]; Whm[i] = W_hm[i];
    }
    for (int i = threadIdx.x; i < 64 * D_IN; i += 256)
        xsm[i] = inputs[((size_t)b * N_NODES + n0) * D_IN + i];
    for (int i = threadIdx.x; i < 64 * D_H; i += 256)
        msm[i] = tanhf(g_msgs[((size_t)b * N_NODES + n0) * D_H + i] + bias[i & 31]);
    __syncthreads();

    const int k = threadIdx.x & 31;
    const int r0 = threadIdx.x >> 5;

    for (int e = 0; e < 8; e++) {
        const int r = r0 + 8 * e;
        float xr = b_ir[k], xi = b_ii[k], xn = b_in[k];
#pragma unroll 8
        for (int d = 0; d < D_IN; d++) {
            float x = xsm[r * D_IN + d];
            xr = fmaf(x, Wir[d * D_H + k], xr);
            xi = fmaf(x, Wii[d * D_H + k], xi);
            xn = fmaf(x, Win[d * D_H + k], xn);
        }
        float hr = 0.f, hi = 0.f, hm = 0.f;
#pragma unroll 8
        for (int d = 0; d < D_H; d++) {
            float mm = msm[r * D_H + d];
            hr = fmaf(mm, Whr[d * D_H + k], hr);
            hi = fmaf(mm, Whi[d * D_H + k], hi);
            hm = fmaf(mm, Whm[d * D_H + k], hm);
        }
        float mg = 1.f / (1.f + __expf(-(xr + hr)));
        float ig = 1.f / (1.f + __expf(-(xi + hi)));
        float nn = tanhf(xn + mg * hm);
        const size_t idx = ((size_t)b * N_NODES + n0 + r) * D_H + k;
        out[idx] = ig * nn + (1.f - ig) * hidden[idx];
    }
}

// ---------------------------------------------------------------------------
// Launch
// ---------------------------------------------------------------------------
extern "C" void kernel_launch(void* const* d_in, const int* in_sizes, int n_in,
                              void* d_out, int out_size) {
    const float* inputs  = (const float*)d_in[0];
    const float* hidden  = (const float*)d_in[1];
    const float* linear  = (const float*)d_in[2];
    const float* bias    = (const float*)d_in[3];
    const float* att_src = (const float*)d_in[4];
    const float* att_tar = (const float*)d_in[5];
    const float* W_hr    = (const float*)d_in[6];
    const float* W_hi    = (const float*)d_in[7];
    const float* W_hm    = (const float*)d_in[8];
    const float* W_ir    = (const float*)d_in[9];
    const float* b_ir    = (const float*)d_in[10];
    const float* W_ii    = (const float*)d_in[11];
    const float* b_ii    = (const float*)d_in[12];
    const float* W_in    = (const float*)d_in[13];
    const float* b_in    = (const float*)d_in[14];
    float* out = (float*)d_out;

    const int att_smem = (N_NODES * D_H + 2 * N_NODES + 4) * sizeof(float);
    const int gru_smem = (3 * D_IN * D_H + 3 * D_H * D_H + 64 * D_IN + 64 * D_H)
                         * sizeof(float);

    static bool attr_done = false;
    if (!attr_done) {
        cudaFuncSetAttribute(att_kernel, cudaFuncAttributeMaxDynamicSharedMemorySize,
                             att_smem);
        cudaFuncSetAttribute(gru_kernel, cudaFuncAttributeMaxDynamicSharedMemorySize,
                             gru_smem);
        attr_done = true;
    }

    proj_kernel<<<H_HEADS * B_SZ * 4, 256>>>(inputs, linear);
    att_kernel<<<H_HEADS * B_SZ * 2, 256, att_smem>>>(att_src, att_tar);
    gru_kernel<<<B_SZ * 8, 256, gru_smem>>>(inputs, hidden, bias,
                                            W_hr, W_hi, W_hm,
                                            W_ir, b_ir, W_ii, b_ii, W_in, b_in,
                                            out);
}

// round 4
// speedup vs baseline: 2.4108x; 1.8542x over previous
#include <cuda_runtime.h>
#include <cstdint>

#define H_HEADS 8
#define D_IN 64
#define D_H 32
#define B_SZ 32
#define N_NODES 512

typedef unsigned long long ull;

// Scratch: h[h][b][n][k]; attention overwrites each slice in place with the
// per-head aggregated messages (no atomics needed).
__device__ float g_h[H_HEADS * B_SZ * N_NODES * D_H];    // 16 MB

__device__ __forceinline__ ull pack2(float x) {
    ull r; asm("mov.b64 %0, {%1, %1};" : "=l"(r) : "f"(x)); return r;
}
__device__ __forceinline__ void ffma2(ull& acc, ull a, ull b) {
    asm("fma.rn.f32x2 %0, %1, %2, %0;" : "+l"(acc) : "l"(a), "l"(b));
}
__device__ __forceinline__ float lo32(ull v) {
    return __uint_as_float((unsigned)(v & 0xffffffffull));
}
__device__ __forceinline__ float hi32(ull v) {
    return __uint_as_float((unsigned)(v >> 32));
}
__device__ __forceinline__ float ex2f(float t) {   // 2^t
    float p; asm("ex2.approx.f32 %0, %1;" : "=f"(p) : "f"(t)); return p;
}
// monotone float->uint map (total order preserved)
__device__ __forceinline__ unsigned flipf(float x) {
    unsigned u = __float_as_uint(x);
    unsigned mask = (unsigned)((int)u >> 31) | 0x80000000u;
    return u ^ mask;
}

#define L2E 1.4426950408889634f
#define C02 0.28853900817779268f   /* 0.2 * log2(e) */

// ---------------------------------------------------------------------------
// Kernel 1: h[h,b,n,k] = sum_d inputs[b,n,d] * linear[h,d,k]
// grid = H*B*8 (64-row segments), 256 threads, 24KB smem.
// Thread = 2 rows x 4 cols, f32x2 packed accumulation.
// ---------------------------------------------------------------------------
__global__ void __launch_bounds__(256) proj_kernel(const float* __restrict__ inputs,
                                                   const float* __restrict__ linear) {
    const int blk = blockIdx.x;
    const int hb = blk >> 3;
    const int seg = blk & 7;
    const int h = hb >> 5;
    const int b = hb & 31;

    __shared__ __align__(16) float Wsm[D_IN * D_H];   // 8 KB
    __shared__ __align__(16) float xsm[64 * D_IN];    // 16 KB

    {
        const float4* W4 = (const float4*)(linear + h * D_IN * D_H);
        float4* Ws4 = (float4*)Wsm;
        for (int i = threadIdx.x; i < D_IN * D_H / 4; i += 256) Ws4[i] = W4[i];
        const float4* x4 = (const float4*)(inputs +
                           ((size_t)b * N_NODES + seg * 64) * D_IN);
        float4* xs4 = (float4*)xsm;
        for (int i = threadIdx.x; i < 64 * D_IN / 4; i += 256) xs4[i] = x4[i];
    }
    __syncthreads();

    const int k4 = threadIdx.x & 7;          // 16B column chunk (4 cols)
    const int r0 = (threadIdx.x >> 3) * 2;   // local row base (0..62)

    ull acc[2][2];
#pragma unroll
    for (int ri = 0; ri < 2; ri++) { acc[ri][0] = 0ull; acc[ri][1] = 0ull; }

    const ulonglong2* Wu = (const ulonglong2*)Wsm;   // 8 x 16B per d-row

    for (int d0 = 0; d0 < D_IN; d0 += 4) {
        float4 xv[2];
#pragma unroll
        for (int ri = 0; ri < 2; ri++)
            xv[ri] = *(const float4*)&xsm[(r0 + ri) * D_IN + d0];
#pragma unroll
        for (int dd = 0; dd < 4; dd++) {
            ulonglong2 wv = Wu[(d0 + dd) * 8 + k4];
#pragma unroll
            for (int ri = 0; ri < 2; ri++) {
                ull x2 = pack2(((const float*)&xv[ri])[dd]);
                ffma2(acc[ri][0], wv.x, x2);
                ffma2(acc[ri][1], wv.y, x2);
            }
        }
    }

    float* out = g_h + ((size_t)hb * N_NODES + seg * 64) * D_H;
#pragma unroll
    for (int ri = 0; ri < 2; ri++) {
        float4 v;
        v.x = lo32(acc[ri][0]); v.y = hi32(acc[ri][0]);
        v.z = lo32(acc[ri][1]); v.w = hi32(acc[ri][1]);
        *(float4*)&out[(r0 + ri) * D_H + k4 * 4] = v;
    }
}

// ---------------------------------------------------------------------------
// Kernel 2: attention via branch factorization + sorted prefix sums.
//   p_ij = exp(lrelu(et_i+es_j)) = u_i*v_j   (s>0)  |  u2_i*v2_j  (s<0)
// Sort j by es_j; prefix sums over sorted order; per-row binary search.
// grid = H*B = 256 blocks, 256 threads, ~212 KB smem, 1 CTA/SM.
// Output overwrites g_h slice in place.
// ---------------------------------------------------------------------------
__global__ void __launch_bounds__(256, 1) att_kernel(const float* __restrict__ att_src,
                                                     const float* __restrict__ att_tar) {
    extern __shared__ float smem[];
    ull*   keys = (ull*)smem;            // 512 ull (= 1024 floats)
    float* hsm  = smem + 1024;           // 512*32
    float* P1   = hsm + 16384;           // 513*32 (row 512 = totals)
    float* P2   = P1 + 16416;            // 513*32
    float* esrc = P2 + 16416;            // 512
    float* etar = esrc + 512;            // 512
    float* vs   = etar + 512;            // 512 (sorted order)
    float* v2s  = vs + 512;              // 512
    float* p1s  = v2s + 512;             // 513 scalar prefix (row 512 = total)
    float* p2s  = p1s + 513;             // 513
    float* Lc1  = p2s + 513;             // 16*32 chunk carries
    float* Lc2  = Lc1 + 512;             // 16*32

    const int hb = blockIdx.x;
    const int h = hb >> 5;
    const int tid = threadIdx.x;
    const int wid = tid >> 5;
    const int lane = tid & 31;

    float* gslice = g_h + (size_t)hb * N_NODES * D_H;

    // ---- load h tile (64 KB) ----
    {
        const float4* src = (const float4*)gslice;
        float4* dst = (float4*)hsm;
        for (int i = tid; i < N_NODES * D_H / 4; i += 256) dst[i] = src[i];
    }
    __syncthreads();

    // ---- e_src / e_tar dot products ----
    {
        const float as = att_src[h * D_H + lane];
        const float at = att_tar[h * D_H + lane];
        for (int j = wid; j < N_NODES; j += 8) {
            float v = hsm[j * D_H + lane];
            float s1 = v * as;
            float s2 = v * at;
#pragma unroll
            for (int off = 16; off; off >>= 1) {
                s1 += __shfl_xor_sync(0xffffffffu, s1, off);
                s2 += __shfl_xor_sync(0xffffffffu, s2, off);
            }
            if (lane == 0) { esrc[j] = s1; etar[j] = s2; }
        }
    }
    __syncthreads();

    // ---- init sort keys: (flip(es_j) << 32) | j ----
    for (int i = tid; i < N_NODES; i += 256)
        keys[i] = ((ull)flipf(esrc[i]) << 32) | (unsigned)i;

    // ---- bitonic sort (ascending) ----
    for (int k2 = 2; k2 <= N_NODES; k2 <<= 1) {
        for (int j2 = k2 >> 1; j2 > 0; j2 >>= 1) {
            __syncthreads();
            for (int i = tid; i < N_NODES; i += 256) {
                int ixj = i ^ j2;
                if (ixj > i) {
                    ull a = keys[i], bb = keys[ixj];
                    bool up = ((i & k2) == 0);
                    if ((a > bb) == up) { keys[i] = bb; keys[ixj] = a; }
                }
            }
        }
    }
    __syncthreads();

    // ---- v, v^0.2 at sorted rank ----
    for (int t = tid; t < N_NODES; t += 256) {
        int j = (int)(unsigned)(keys[t] & 0xffffffffull);
        float e = esrc[j];
        vs[t]  = ex2f(e * L2E);
        v2s[t] = ex2f(e * C02);
    }
    __syncthreads();

    // ---- pass A: per-chunk (32-rank) partial sums of v*h and v2*h ----
    {
        const int k = lane;
        for (int cc = wid; cc < 16; cc += 8) {
            float l1 = 0.f, l2 = 0.f;
#pragma unroll 4
            for (int tt = 0; tt < 32; tt++) {
                int t = cc * 32 + tt;
                int j = (int)(unsigned)(keys[t] & 0xffffffffull);
                float x = hsm[j * D_H + k];
                l1 = fmaf(vs[t], x, l1);
                l2 = fmaf(v2s[t], x, l2);
            }
            Lc1[cc * 32 + k] = l1;
            Lc2[cc * 32 + k] = l2;
        }
    }
    __syncthreads();

    // ---- pass B: scan chunk carries; scalar prefix scans ----
    if (wid == 0) {                 // Lc1 -> exclusive, totals -> P1 row 512
        float run = 0.f;
#pragma unroll
        for (int cc = 0; cc < 16; cc++) {
            float tmp = Lc1[cc * 32 + lane];
            Lc1[cc * 32 + lane] = run;
            run += tmp;
        }
        P1[512 * D_H + lane] = run;
    } else if (wid == 1) {
        float run = 0.f;
#pragma unroll
        for (int cc = 0; cc < 16; cc++) {
            float tmp = Lc2[cc * 32 + lane];
            Lc2[cc * 32 + lane] = run;
            run += tmp;
        }
        P2[512 * D_H + lane] = run;
    } else if (wid == 2 || wid == 3) {   // scalar prefixes of v / v2
        float* dst = (wid == 2) ? p1s : p2s;
        const float* src = (wid == 2) ? vs : v2s;
        float carry = 0.f;
        for (int c = 0; c < 16; c++) {
            float x = src[c * 32 + lane];
            float inc = x;
#pragma unroll
            for (int off = 1; off < 32; off <<= 1) {
                float y = __shfl_up_sync(0xffffffffu, inc, off);
                if (lane >= off) inc += y;
            }
            dst[c * 32 + lane] = carry + inc - x;   // exclusive
            carry += __shfl_sync(0xffffffffu, inc, 31);
        }
        if (lane == 0) dst[512] = carry;
    }
    __syncthreads();

    // ---- pass C: write full exclusive prefix arrays ----
    {
        const int k = lane;
        for (int cc = wid; cc < 16; cc += 8) {
            float r1 = Lc1[cc * 32 + k];
            float r2 = Lc2[cc * 32 + k];
#pragma unroll 4
            for (int tt = 0; tt < 32; tt++) {
                int t = cc * 32 + tt;
                P1[t * D_H + k] = r1;
                P2[t * D_H + k] = r2;
                int j = (int)(unsigned)(keys[t] & 0xffffffffull);
                float x = hsm[j * D_H + k];
                r1 = fmaf(vs[t], x, r1);
                r2 = fmaf(v2s[t], x, r2);
            }
        }
    }
    __syncthreads();

    // ---- per-row combine ----
    const float T1s = p1s[512];
    const float4* P14 = (const float4*)P1;
    const float4* P24 = (const float4*)P2;
    const float4* hsm4 = (const float4*)hsm;
    float4* out4 = (float4*)gslice;

#pragma unroll
    for (int rr = 0; rr < 2; rr++) {
        const int i = tid + rr * 256;
        const float et = etar[i];
        const float u  = ex2f(et * L2E);
        const float u2 = ex2f(et * C02);

        // t = #{j : es_j < -et}
        const ull target = ((ull)flipf(-et)) << 32;
        int lo = 0, hi = N_NODES;
#pragma unroll
        for (int it = 0; it < 9; it++) {
            int mid = (lo + hi) >> 1;
            if (keys[mid] < target) lo = mid + 1; else hi = mid;
        }
        const int t = lo;

        // self term (exact branch)
        float s = et + esrc[i];
        float ts = fmaf(fmaxf(s, 0.f), L2E, fminf(s, 0.f) * C02);
        float ps = ex2f(ts);

        float denom = u * (T1s - p1s[t]) + u2 * p2s[t] - ps;
        float sc = 1.f / denom;

#pragma unroll
        for (int c = 0; c < 8; c++) {
            float4 tot = P14[512 * 8 + c];
            float4 a1 = P14[t * 8 + c];
            float4 a2 = P24[t * 8 + c];
            float4 hv = hsm4[i * 8 + c];
            float4 r;
            r.x = (u * (tot.x - a1.x) + u2 * a2.x - ps * hv.x) * sc;
            r.y = (u * (tot.y - a1.y) + u2 * a2.y - ps * hv.y) * sc;
            r.z = (u * (tot.z - a1.z) + u2 * a2.z - ps * hv.z) * sc;
            r.w = (u * (tot.w - a1.w) + u2 * a2.w - ps * hv.w) * sc;
            out4[i * 8 + c] = r;
        }
    }
}

// ---------------------------------------------------------------------------
// Kernel 3: msgs = tanh(mean_h(head_msgs) + bias); GRU gated update -> out
// grid = B * 8 (64-row chunks), 256 threads
// ---------------------------------------------------------------------------
__global__ void gru_kernel(const float* __restrict__ inputs,
                           const float* __restrict__ hidden,
                           const float* __restrict__ bias,
                           const float* __restrict__ W_hr,
                           const float* __restrict__ W_hi,
                           const float* __restrict__ W_hm,
                           const float* __restrict__ W_ir,
                           const float* __restrict__ b_ir,
                           const float* __restrict__ W_ii,
                           const float* __restrict__ b_ii,
                           const float* __restrict__ W_in,
                           const float* __restrict__ b_in,
                           float* __restrict__ out) {
    extern __shared__ float smem[];
    float* Wir = smem;                    // 2048
    float* Wii = Wir + D_IN * D_H;        // 2048
    float* Win = Wii + D_IN * D_H;        // 2048
    float* Whr = Win + D_IN * D_H;        // 1024
    float* Whi = Whr + D_H * D_H;         // 1024
    float* Whm = Whi + D_H * D_H;         // 1024
    float* xsm = Whm + D_H * D_H;         // 64*64
    float* msm = xsm + 64 * D_IN;         // 64*32

    const int b = blockIdx.x >> 3;
    const int n0 = (blockIdx.x & 7) * 64;

    for (int i = threadIdx.x; i < D_IN * D_H; i += 256) {
        Wir[i] = W_ir[i]; Wii[i] = W_ii[i]; Win[i] = W_in[i];
    }
    for (int i = threadIdx.x; i < D_H * D_H; i += 256) {
        Whr[i] = W_hr[i]; Whi[i] = W_hi[i]; Whm[i] = W_hm[i];
    }
    for (int i = threadIdx.x; i < 64 * D_IN / 4; i += 256)
        ((float4*)xsm)[i] =
            ((const float4*)(inputs + ((size_t)b * N_NODES + n0) * D_IN))[i];

    // mean over heads + bias + tanh
    for (int i = threadIdx.x; i < 64 * D_H / 4; i += 256) {
        float4 acc = make_float4(0.f, 0.f, 0.f, 0.f);
#pragma unroll
        for (int h = 0; h < H_HEADS; h++) {
            const float4* src = (const float4*)(g_h +
                ((size_t)(h * B_SZ + b) * N_NODES + n0) * D_H);
            float4 v = src[i];
            acc.x += v.x; acc.y += v.y; acc.z += v.z; acc.w += v.w;
        }
        int k4 = (i & 7) * 4;
        float4 r;
        r.x = tanhf(acc.x * 0.125f + bias[k4 + 0]);
        r.y = tanhf(acc.y * 0.125f + bias[k4 + 1]);
        r.z = tanhf(acc.z * 0.125f + bias[k4 + 2]);
        r.w = tanhf(acc.w * 0.125f + bias[k4 + 3]);
        ((float4*)msm)[i] = r;
    }
    __syncthreads();

    const int k = threadIdx.x & 31;
    const int r0 = threadIdx.x >> 5;

    for (int e = 0; e < 8; e++) {
        const int r = r0 + 8 * e;
        float xr = b_ir[k], xi = b_ii[k], xn = b_in[k];
#pragma unroll 8
        for (int d = 0; d < D_IN; d++) {
            float x = xsm[r * D_IN + d];
            xr = fmaf(x, Wir[d * D_H + k], xr);
            xi = fmaf(x, Wii[d * D_H + k], xi);
            xn = fmaf(x, Win[d * D_H + k], xn);
        }
        float hr = 0.f, hi = 0.f, hm = 0.f;
#pragma unroll 8
        for (int d = 0; d < D_H; d++) {
            float mm = msm[r * D_H + d];
            hr = fmaf(mm, Whr[d * D_H + k], hr);
            hi = fmaf(mm, Whi[d * D_H + k], hi);
            hm = fmaf(mm, Whm[d * D_H + k], hm);
        }
        float mg = 1.f / (1.f + __expf(-(xr + hr)));
        float ig = 1.f / (1.f + __expf(-(xi + hi)));
        float nn = tanhf(xn + mg * hm);
        const size_t idx = ((size_t)b * N_NODES + n0 + r) * D_H + k;
        out[idx] = ig * nn + (1.f - ig) * hidden[idx];
    }
}

// ---------------------------------------------------------------------------
// Launch
// ---------------------------------------------------------------------------
extern "C" void kernel_launch(void* const* d_in, const int* in_sizes, int n_in,
                              void* d_out, int out_size) {
    const float* inputs  = (const float*)d_in[0];
    const float* hidden  = (const float*)d_in[1];
    const float* linear  = (const float*)d_in[2];
    const float* bias    = (const float*)d_in[3];
    const float* att_src = (const float*)d_in[4];
    const float* att_tar = (const float*)d_in[5];
    const float* W_hr    = (const float*)d_in[6];
    const float* W_hi    = (const float*)d_in[7];
    const float* W_hm    = (const float*)d_in[8];
    const float* W_ir    = (const float*)d_in[9];
    const float* b_ir    = (const float*)d_in[10];
    const float* W_ii    = (const float*)d_in[11];
    const float* b_ii    = (const float*)d_in[12];
    const float* W_in    = (const float*)d_in[13];
    const float* b_in    = (const float*)d_in[14];
    float* out = (float*)d_out;

    const int att_smem = (1024 + 16384 + 2 * 16416 + 4 * 512 + 2 * 513 + 2 * 512)
                         * sizeof(float);                                  // 217352
    const int gru_smem = (3 * D_IN * D_H + 3 * D_H * D_H + 64 * D_IN + 64 * D_H)
                         * sizeof(float);                                  // 61440

    static bool attr_done = false;
    if (!attr_done) {
        cudaFuncSetAttribute(att_kernel, cudaFuncAttributeMaxDynamicSharedMemorySize,
                             att_smem);
        cudaFuncSetAttribute(gru_kernel, cudaFuncAttributeMaxDynamicSharedMemorySize,
                             gru_smem);
        attr_done = true;
    }

    proj_kernel<<<H_HEADS * B_SZ * 8, 256>>>(inputs, linear);
    att_kernel<<<H_HEADS * B_SZ, 256, att_smem>>>(att_src, att_tar);
    gru_kernel<<<B_SZ * 8, 256, gru_smem>>>(inputs, hidden, bias,
                                            W_hr, W_hi, W_hm,
                                            W_ir, b_ir, W_ii, b_ii, W_in, b_in,
                                            out);
}

// round 6
// speedup vs baseline: 2.9231x; 1.2125x over previous
#include <cuda_runtime.h>
#include <cstdint>

#define H_HEADS 8
#define D_IN 64
#define D_H 32
#define B_SZ 32
#define N_NODES 512

typedef unsigned long long ull;

// Scratch: h[h][b][n][k]; attention overwrites each slice in place with the
// per-head aggregated messages; gru sums heads.
__device__ float g_h[H_HEADS * B_SZ * N_NODES * D_H];    // 16 MB

__device__ __forceinline__ ull pack2(float x) {
    ull r; asm("mov.b64 %0, {%1, %1};" : "=l"(r) : "f"(x)); return r;
}
__device__ __forceinline__ void ffma2(ull& acc, ull a, ull b) {
    asm("fma.rn.f32x2 %0, %1, %2, %0;" : "+l"(acc) : "l"(a), "l"(b));
}
__device__ __forceinline__ float lo32(ull v) {
    return __uint_as_float((unsigned)(v & 0xffffffffull));
}
__device__ __forceinline__ float hi32(ull v) {
    return __uint_as_float((unsigned)(v >> 32));
}
__device__ __forceinline__ float ex2f(float t) {   // 2^t
    float p; asm("ex2.approx.f32 %0, %1;" : "=f"(p) : "f"(t)); return p;
}
// monotone float->uint map (total order preserved)
__device__ __forceinline__ unsigned flipf(float x) {
    unsigned u = __float_as_uint(x);
    unsigned mask = (unsigned)((int)u >> 31) | 0x80000000u;
    return u ^ mask;
}
__device__ __forceinline__ float unflipf(unsigned u) {
    unsigned mask = (u & 0x80000000u) ? 0x80000000u : 0xffffffffu;
    return __uint_as_float(u ^ mask);
}

#define L2E 1.4426950408889634f
#define C02 0.28853900817779268f   /* 0.2 * log2(e) */
#define XPAD 72                    /* padded row stride (floats) */

// ---------------------------------------------------------------------------
// Kernel 1: h[h,b,n,k] = sum_d inputs[b,n,d] * linear[h,d,k]
// grid = H*B*2 (256-row segments), 256 threads.
// Thread = 8 rows (stride 32) x 4 cols; W reused 8x per LDS.
// ---------------------------------------------------------------------------
__global__ void __launch_bounds__(256) proj_kernel(const float* __restrict__ inputs,
                                                   const float* __restrict__ linear) {
    const int blk = blockIdx.x;
    const int hb = blk >> 1;
    const int seg = blk & 1;
    const int h = hb >> 5;
    const int b = hb & 31;

    __shared__ __align__(16) float Wsm[D_IN * D_H];     // 8 KB
    __shared__ __align__(16) float xsm[256 * XPAD];     // 72 KB

    {
        const float4* W4 = (const float4*)(linear + h * D_IN * D_H);
        float4* Ws4 = (float4*)Wsm;
        for (int i = threadIdx.x; i < D_IN * D_H / 4; i += 256) Ws4[i] = W4[i];
        const float4* xin4 = (const float4*)(inputs +
                             ((size_t)b * N_NODES + seg * 256) * D_IN);
        for (int i = threadIdx.x; i < 256 * D_IN / 4; i += 256) {
            int r = i >> 4, d4 = i & 15;
            *(float4*)&xsm[r * XPAD + d4 * 4] = xin4[i];
        }
    }
    __syncthreads();

    const int k4 = threadIdx.x & 7;     // 16B column chunk (4 cols)
    const int rg = threadIdx.x >> 3;    // 0..31; rows rg + 32*ri

    ull acc[8][2];
#pragma unroll
    for (int ri = 0; ri < 8; ri++) { acc[ri][0] = 0ull; acc[ri][1] = 0ull; }

    const ulonglong2* Wu = (const ulonglong2*)Wsm;   // 8 x 16B per d-row

#pragma unroll 4
    for (int d0 = 0; d0 < D_IN; d0 += 4) {
        float4 xv[8];
#pragma unroll
        for (int ri = 0; ri < 8; ri++)
            xv[ri] = *(const float4*)&xsm[(rg + 32 * ri) * XPAD + d0];
#pragma unroll
        for (int dd = 0; dd < 4; dd++) {
            ulonglong2 wv = Wu[(d0 + dd) * 8 + k4];
#pragma unroll
            for (int ri = 0; ri < 8; ri++) {
                ull x2 = pack2(((const float*)&xv[ri])[dd]);
                ffma2(acc[ri][0], wv.x, x2);
                ffma2(acc[ri][1], wv.y, x2);
            }
        }
    }

    float* out = g_h + ((size_t)hb * N_NODES + seg * 256) * D_H;
#pragma unroll
    for (int ri = 0; ri < 8; ri++) {
        int r = rg + 32 * ri;
        float4 v;
        v.x = lo32(acc[ri][0]); v.y = hi32(acc[ri][0]);
        v.z = lo32(acc[ri][1]); v.w = hi32(acc[ri][1]);
        *(float4*)&out[r * D_H + k4 * 4] = v;
    }
}

// ---------------------------------------------------------------------------
// Kernel 2: attention via branch factorization + double sort + merge sweep.
//   p_ij = exp(lrelu(et_i+es_j)) = u_i*v_j (s>0) | u2_i*v2_j (s<0)
// Sort j by es_j AND rows i by -et_i. Thresholds t_i are then monotone, so
// one running prefix per warp suffices (no materialized prefix arrays).
// grid = H*B = 256 blocks, 256 threads, ~84 KB smem -> 2 CTA/SM, 1 wave.
// Output overwrites g_h slice in place.
// ---------------------------------------------------------------------------
__global__ void __launch_bounds__(256, 2) att_kernel(const float* __restrict__ att_src,
                                                     const float* __restrict__ att_tar) {
    extern __shared__ float smem[];
    ull*   keys  = (ull*)smem;                 // [512] by es (asc)
    ull*   keys2 = keys + 512;                 // [512] by -et (asc)
    float* hsm   = (float*)(keys2 + 512);      // 512*32
    float* esrc  = hsm + N_NODES * D_H;        // 512
    float* etar  = esrc + 512;                 // 512
    float* vs    = etar + 512;                 // 512 sorted exp(es)
    float* v2s   = vs + 512;                   // 512 sorted exp(0.2 es)
    float* Lc1   = v2s + 512;                  // 9*32 (excl. chunk carries, [8]=total)
    float* Lc2   = Lc1 + 288;                  // 9*32
    float* cv1   = Lc2 + 288;                  // 9
    float* cv2   = cv1 + 9;                    // 9

    const int hb = blockIdx.x;
    const int h = hb >> 5;
    const int tid = threadIdx.x;
    const int wid = tid >> 5;
    const int lane = tid & 31;

    float* gslice = g_h + (size_t)hb * N_NODES * D_H;

    // ---- load h tile (64 KB) ----
    {
        const float4* src = (const float4*)gslice;
        float4* dst = (float4*)hsm;
        for (int i = tid; i < N_NODES * D_H / 4; i += 256) dst[i] = src[i];
    }
    __syncthreads();

    // ---- e_src / e_tar dot products ----
    {
        const float as = att_src[h * D_H + lane];
        const float at = att_tar[h * D_H + lane];
        for (int j = wid; j < N_NODES; j += 8) {
            float v = hsm[j * D_H + lane];
            float s1 = v * as;
            float s2 = v * at;
#pragma unroll
            for (int off = 16; off; off >>= 1) {
                s1 += __shfl_xor_sync(0xffffffffu, s1, off);
                s2 += __shfl_xor_sync(0xffffffffu, s2, off);
            }
            if (lane == 0) { esrc[j] = s1; etar[j] = s2; }
        }
    }
    __syncthreads();

    // ---- sort keys: keys by es_j asc; keys2 by -et_i asc ----
    for (int i = tid; i < N_NODES; i += 256) {
        keys[i]  = ((ull)flipf(esrc[i]) << 32) | (unsigned)i;
        keys2[i] = ((ull)flipf(-etar[i]) << 32) | (unsigned)i;
    }
    for (int k2 = 2; k2 <= N_NODES; k2 <<= 1) {
        for (int j2 = k2 >> 1; j2 > 0; j2 >>= 1) {
            __syncthreads();
            for (int i = tid; i < 2 * N_NODES; i += 256) {
                ull* arr = (i < N_NODES) ? keys : keys2;
                int idx = i & (N_NODES - 1);
                int ixj = idx ^ j2;
                if (ixj > idx) {
                    ull a = arr[idx], bb = arr[ixj];
                    if ((a > bb) == ((idx & k2) == 0)) { arr[idx] = bb; arr[ixj] = a; }
                }
            }
        }
    }
    __syncthreads();

    // ---- v = exp(es), v2 = exp(0.2 es) at sorted rank (from key bits) ----
    for (int t = tid; t < N_NODES; t += 256) {
        float e = unflipf((unsigned)(keys[t] >> 32));
        vs[t]  = ex2f(e * L2E);
        v2s[t] = ex2f(e * C02);
    }
    __syncthreads();

    // ---- per-chunk (64-rank) partial sums ----
    {
        const int c = wid;
        const int k = lane;
        float l1 = 0.f, l2 = 0.f;
#pragma unroll 4
        for (int tt = 0; tt < 64; tt++) {
            int t = c * 64 + tt;
            int j = (int)(unsigned)(keys[t] & 0xffffffffull);
            float x = hsm[j * D_H + k];
            l1 = fmaf(vs[t], x, l1);
            l2 = fmaf(v2s[t], x, l2);
        }
        Lc1[c * 32 + k] = l1;
        Lc2[c * 32 + k] = l2;
        // scalar chunk sums
        float s1 = vs[c * 64 + lane] + vs[c * 64 + 32 + lane];
        float s2 = v2s[c * 64 + lane] + v2s[c * 64 + 32 + lane];
#pragma unroll
        for (int off = 16; off; off >>= 1) {
            s1 += __shfl_xor_sync(0xffffffffu, s1, off);
            s2 += __shfl_xor_sync(0xffffffffu, s2, off);
        }
        if (lane == 0) { cv1[c] = s1; cv2[c] = s2; }
    }
    __syncthreads();

    // ---- exclusive scan of chunk carries ----
    if (wid == 0) {
        float run = 0.f;
#pragma unroll
        for (int c = 0; c < 8; c++) {
            float t = Lc1[c * 32 + lane]; Lc1[c * 32 + lane] = run; run += t;
        }
        Lc1[256 + lane] = run;
    } else if (wid == 1) {
        float run = 0.f;
#pragma unroll
        for (int c = 0; c < 8; c++) {
            float t = Lc2[c * 32 + lane]; Lc2[c * 32 + lane] = run; run += t;
        }
        Lc2[256 + lane] = run;
    } else if (wid == 2 && lane == 0) {
        float r1 = 0.f, r2 = 0.f;
#pragma unroll
        for (int c = 0; c < 8; c++) {
            float a = cv1[c], b2 = cv2[c];
            cv1[c] = r1; cv2[c] = r2;
            r1 += a; r2 += b2;
        }
        cv1[8] = r1; cv2[8] = r2;
    }
    __syncthreads();

    // ---- merge sweep: warp w handles sorted rows [64w, 64w+64) ----
    {
        const int w = wid;
        const int k = lane;

        // first row's threshold -> starting chunk
        ull target0 = (keys2[w * 64] >> 32) << 32;
        int lo = 0, hi = N_NODES;
#pragma unroll
        for (int it = 0; it < 9; it++) {
            int mid = (lo + hi) >> 1;
            if (keys[mid] < target0) lo = mid + 1; else hi = mid;
        }
        const int c0 = lo >> 6;
        int t_cur = c0 << 6;

        float S1 = Lc1[c0 * 32 + k];
        float S2 = Lc2[c0 * 32 + k];
        float Sv1 = cv1[c0];
        float Sv2 = cv2[c0];
        const float T1k = Lc1[256 + k];
        const float Tv1 = cv1[8];

        for (int r = 0; r < 64; r++) {
            ull k2v = keys2[w * 64 + r];
            int i = (int)(unsigned)(k2v & 0xffffffffull);
            ull target = (k2v >> 32) << 32;
            while (t_cur < N_NODES) {
                ull kk = keys[t_cur];
                if (kk >= target) break;
                int j = (int)(unsigned)(kk & 0xffffffffull);
                float x = hsm[j * D_H + k];
                float a = vs[t_cur], b2 = v2s[t_cur];
                S1 = fmaf(a, x, S1);
                S2 = fmaf(b2, x, S2);
                Sv1 += a; Sv2 += b2;
                t_cur++;
            }
            float et = etar[i];
            float es = esrc[i];
            float u  = ex2f(et * L2E);
            float u2 = ex2f(et * C02);
            float s = et + es;
            float ps = ex2f(fmaf(fmaxf(s, 0.f), L2E, fminf(s, 0.f) * C02));
            float denom = u * (Tv1 - Sv1) + u2 * Sv2 - ps;
            float sc = 1.f / denom;
            float hx = hsm[i * D_H + k];
            gslice[i * D_H + k] = (u * (T1k - S1) + u2 * S2 - ps * hx) * sc;
        }
    }
}

// ---------------------------------------------------------------------------
// Kernel 3: msgs = tanh(mean_h(head_msgs) + bias); GRU gated update -> out
// grid = B * 8 (64-row chunks), 256 threads
// ---------------------------------------------------------------------------
__global__ void gru_kernel(const float* __restrict__ inputs,
                           const float* __restrict__ hidden,
                           const float* __restrict__ bias,
                           const float* __restrict__ W_hr,
                           const float* __restrict__ W_hi,
                           const float* __restrict__ W_hm,
                           const float* __restrict__ W_ir,
                           const float* __restrict__ b_ir,
                           const float* __restrict__ W_ii,
                           const float* __restrict__ b_ii,
                           const float* __restrict__ W_in,
                           const float* __restrict__ b_in,
                           float* __restrict__ out) {
    extern __shared__ float smem[];
    float* Wir = smem;                    // 2048
    float* Wii = Wir + D_IN * D_H;        // 2048
    float* Win = Wii + D_IN * D_H;        // 2048
    float* Whr = Win + D_IN * D_H;        // 1024
    float* Whi = Whr + D_H * D_H;         // 1024
    float* Whm = Whi + D_H * D_H;         // 1024
    float* xsm = Whm + D_H * D_H;         // 64*64
    float* msm = xsm + 64 * D_IN;         // 64*32

    const int b = blockIdx.x >> 3;
    const int n0 = (blockIdx.x & 7) * 64;

    for (int i = threadIdx.x; i < D_IN * D_H; i += 256) {
        Wir[i] = W_ir[i]; Wii[i] = W_ii[i]; Win[i] = W_in[i];
    }
    for (int i = threadIdx.x; i < D_H * D_H; i += 256) {
        Whr[i] = W_hr[i]; Whi[i] = W_hi[i]; Whm[i] = W_hm[i];
    }
    for (int i = threadIdx.x; i < 64 * D_IN / 4; i += 256)
        ((float4*)xsm)[i] =
            ((const float4*)(inputs + ((size_t)b * N_NODES + n0) * D_IN))[i];

    // mean over heads + bias + tanh
    for (int i = threadIdx.x; i < 64 * D_H / 4; i += 256) {
        float4 acc = make_float4(0.f, 0.f, 0.f, 0.f);
#pragma unroll
        for (int h = 0; h < H_HEADS; h++) {
            const float4* src = (const float4*)(g_h +
                ((size_t)(h * B_SZ + b) * N_NODES + n0) * D_H);
            float4 v = src[i];
            acc.x += v.x; acc.y += v.y; acc.z += v.z; acc.w += v.w;
        }
        int k4 = (i & 7) * 4;
        float4 r;
        r.x = tanhf(acc.x * 0.125f + bias[k4 + 0]);
        r.y = tanhf(acc.y * 0.125f + bias[k4 + 1]);
        r.z = tanhf(acc.z * 0.125f + bias[k4 + 2]);
        r.w = tanhf(acc.w * 0.125f + bias[k4 + 3]);
        ((float4*)msm)[i] = r;
    }
    __syncthreads();

    const int k = threadIdx.x & 31;
    const int r0 = threadIdx.x >> 5;

    for (int e = 0; e < 8; e++) {
        const int r = r0 + 8 * e;
        float xr = b_ir[k], xi = b_ii[k], xn = b_in[k];
#pragma unroll 8
        for (int d = 0; d < D_IN; d++) {
            float x = xsm[r * D_IN + d];
            xr = fmaf(x, Wir[d * D_H + k], xr);
            xi = fmaf(x, Wii[d * D_H + k], xi);
            xn = fmaf(x, Win[d * D_H + k], xn);
        }
        float hr = 0.f, hi = 0.f, hm = 0.f;
#pragma unroll 8
        for (int d = 0; d < D_H; d++) {
            float mm = msm[r * D_H + d];
            hr = fmaf(mm, Whr[d * D_H + k], hr);
            hi = fmaf(mm, Whi[d * D_H + k], hi);
            hm = fmaf(mm, Whm[d * D_H + k], hm);
        }
        float mg = 1.f / (1.f + __expf(-(xr + hr)));
        float ig = 1.f / (1.f + __expf(-(xi + hi)));
        float nn = tanhf(xn + mg * hm);
        const size_t idx = ((size_t)b * N_NODES + n0 + r) * D_H + k;
        out[idx] = ig * nn + (1.f - ig) * hidden[idx];
    }
}

// ---------------------------------------------------------------------------
// Launch
// ---------------------------------------------------------------------------
extern "C" void kernel_launch(void* const* d_in, const int* in_sizes, int n_in,
                              void* d_out, int out_size) {
    const float* inputs  = (const float*)d_in[0];
    const float* hidden  = (const float*)d_in[1];
    const float* linear  = (const float*)d_in[2];
    const float* bias    = (const float*)d_in[3];
    const float* att_src = (const float*)d_in[4];
    const float* att_tar = (const float*)d_in[5];
    const float* W_hr    = (const float*)d_in[6];
    const float* W_hi    = (const float*)d_in[7];
    const float* W_hm    = (const float*)d_in[8];
    const float* W_ir    = (const float*)d_in[9];
    const float* b_ir    = (const float*)d_in[10];
    const float* W_ii    = (const float*)d_in[11];
    const float* b_ii    = (const float*)d_in[12];
    const float* W_in    = (const float*)d_in[13];
    const float* b_in    = (const float*)d_in[14];
    float* out = (float*)d_out;

    const int att_smem = (1024 + 1024 + N_NODES * D_H + 4 * 512 + 2 * 288 + 18)
                         * sizeof(float);                                  // 84296
    const int gru_smem = (3 * D_IN * D_H + 3 * D_H * D_H + 64 * D_IN + 64 * D_H)
                         * sizeof(float);                                  // 61440

    static bool attr_done = false;
    if (!attr_done) {
        cudaFuncSetAttribute(att_kernel, cudaFuncAttributeMaxDynamicSharedMemorySize,
                             att_smem);
        cudaFuncSetAttribute(gru_kernel, cudaFuncAttributeMaxDynamicSharedMemorySize,
                             gru_smem);
        attr_done = true;
    }

    proj_kernel<<<H_HEADS * B_SZ * 2, 256>>>(inputs, linear);
    att_kernel<<<H_HEADS * B_SZ, 256, att_smem>>>(att_src, att_tar);
    gru_kernel<<<B_SZ * 8, 256, gru_smem>>>(inputs, hidden, bias,
                                            W_hr, W_hi, W_hm,
                                            W_ir, b_ir, W_ii, b_ii, W_in, b_in,
                                            out);
}